// round 13
// baseline (speedup 1.0000x reference)
#include <cuda_runtime.h>
#include <cuda_fp16.h>
#include <math.h>
#include <stdint.h>

#define TM      128
#define KNB     27
#define MAXN    150000

// kconvA: A0 16K | A1 16K | W 32K = 64KB  -> 3 blocks/SM
#define A_A0   0
#define A_A1   16384
#define A_W    32768
// kconvB: Ag 16K | Ah 16K | W 32K = 64KB -> 3 blocks/SM
#define B_AG   0
#define B_AH   16384
#define B_W    32768
#define SMEM_BYTES 65536

// ------------------------- device scratch -------------------------
// f16 gather tables: row n = 128B (64 f16)
__device__ __align__(16) char g_x2b[(size_t)MAXN * 128];
__device__ __align__(16) char g_hgb[(size_t)MAXN * 128];
__device__ __align__(16) char g_hhb[(size_t)MAXN * 128];
__device__ __align__(16) char g_y1b[(size_t)MAXN * 128];
__device__ int g_idxT[KNB * MAXN];
// W planes f16, swizzled [kk][n]: hi + lo (8 conv tensors x 27 planes; 4 dense)
__device__ __align__(16) __half g_wch[8 * 27 * 4096];
__device__ __align__(16) __half g_wcl[8 * 27 * 4096];
__device__ __align__(16) __half g_wdh[4 * 4096];
__device__ __align__(16) __half g_wdl[4 * 4096];

// ------------------------- helpers -------------------------
__device__ __forceinline__ uint32_t smem_u32(const void* p) {
    uint32_t a;
    asm("{ .reg .u64 t; cvta.to.shared.u64 t, %1; cvt.u32.u64 %0, t; }" : "=r"(a) : "l"(p));
    return a;
}
__device__ __forceinline__ float lrelu(float v) { return v >= 0.f ? v : 0.2f * v; }
__device__ __forceinline__ uint32_t pack_h2(float lo_elem, float hi_elem) {
    uint32_t r;
    asm("cvt.rn.f16x2.f32 %0, %1, %2;" : "=r"(r) : "f"(hi_elem), "f"(lo_elem));
    return r;
}
__device__ __forceinline__ void cp16(uint32_t dst, const char* src) {
    asm volatile("cp.async.cg.shared.global [%0], [%1], 16;" :: "r"(dst), "l"(src));
}
#define CP_COMMIT() asm volatile("cp.async.commit_group;" ::: "memory")
#define CP_WAIT0()  asm volatile("cp.async.wait_group 0;" ::: "memory")
#define CP_WAIT1()  asm volatile("cp.async.wait_group 1;" ::: "memory")

__device__ __forceinline__ void ldsm4(uint32_t* r, uint32_t a) {
    asm volatile("ldmatrix.sync.aligned.m8n8.x4.shared.b16 {%0,%1,%2,%3}, [%4];"
                 : "=r"(r[0]), "=r"(r[1]), "=r"(r[2]), "=r"(r[3]) : "r"(a));
}
__device__ __forceinline__ void ldsm4t(uint32_t* r, uint32_t a) {
    asm volatile("ldmatrix.sync.aligned.m8n8.x4.trans.shared.b16 {%0,%1,%2,%3}, [%4];"
                 : "=r"(r[0]), "=r"(r[1]), "=r"(r[2]), "=r"(r[3]) : "r"(a));
}
__device__ __forceinline__ void mma_f16(float* d, const uint32_t* a, const uint32_t* b) {
    asm volatile(
        "mma.sync.aligned.m16n8k16.row.col.f32.f16.f16.f32 "
        "{%0,%1,%2,%3}, {%4,%5,%6,%7}, {%8,%9}, {%0,%1,%2,%3};"
        : "+f"(d[0]), "+f"(d[1]), "+f"(d[2]), "+f"(d[3])
        : "r"(a[0]), "r"(a[1]), "r"(a[2]), "r"(a[3]), "r"(b[0]), "r"(b[1]));
}

// ------------------------- prep kernels (R12-identical) -------------------
__global__ void kprep_conv(const float* w0, const float* w1, const float* w2,
                           const float* w3, const float* w4, const float* w5,
                           const float* w6, const float* w7) {
    int e = blockIdx.x * 256 + threadIdx.x;
    const int per = 27 * 4096;
    if (e >= 8 * per) return;
    int ti = e / per, r = e % per;
    int k = r >> 12, p = r & 4095;
    int kk = p >> 6, n = p & 63;
    const float* ws[8] = {w0, w1, w2, w3, w4, w5, w6, w7};
    float v = ws[ti][(size_t)k * 4096 + kk * 64 + n];
    __half hh = __float2half_rn(v);
    __half hl = __float2half_rn(v - __half2float(hh));
    int off = kk * 128 + (((n >> 3) ^ (kk & 7)) << 4) + (n & 7) * 2;
    size_t base = ((size_t)ti * 27 + k) * 8192;
    *(__half*)((char*)g_wch + base + off) = hh;
    *(__half*)((char*)g_wcl + base + off) = hl;
}
__global__ void kprep_dense(const float* w0, const float* w1,
                            const float* w2, const float* w3) {
    int e = blockIdx.x * 256 + threadIdx.x;
    if (e >= 4 * 4096) return;
    int ti = e >> 12, p = e & 4095;
    int kk = p >> 6, n = p & 63;
    const float* ws[4] = {w0, w1, w2, w3};
    float v = ws[ti][kk * 64 + n];
    __half hh = __float2half_rn(v);
    __half hl = __float2half_rn(v - __half2float(hh));
    int off = kk * 128 + (((n >> 3) ^ (kk & 7)) << 4) + (n & 7) * 2;
    size_t base = (size_t)ti * 8192;
    *(__half*)((char*)g_wdh + base + off) = hh;
    *(__half*)((char*)g_wdl + base + off) = hl;
}
__global__ void kprep_idx(const int* __restrict__ idx, int N) {
    int e = blockIdx.x * 256 + threadIdx.x;
    if (e >= N * KNB) return;
    g_idxT[(size_t)(e % KNB) * N + (e / KNB)] = idx[e];
}
__global__ void kprep_x2(const float* __restrict__ x, int N) {
    int e = blockIdx.x * 256 + threadIdx.x;
    if (e >= N * 32) return;
    int n = e >> 5, c = (e & 31) * 2;
    float v0 = x[(size_t)n * 128 + 64 + c];
    float v1 = x[(size_t)n * 128 + 64 + c + 1];
    *(uint32_t*)(g_x2b + (size_t)n * 128 + c * 2) = pack_h2(v0, v1);
}

// ------------------------- staging (256 threads) -------------------------
__device__ __forceinline__ void gather_cp(uint32_t dst,
    const char* __restrict__ tab, const int* __restrict__ idxT,
    int k, int nbase, int N, int t)
{
    int row = t >> 1, h = t & 1;
    int n = nbase + row; if (n >= N) n = N - 1;
    size_t g = (size_t)idxT[(size_t)k * N + n] * 128;
#pragma unroll
    for (int c = 0; c < 4; ++c) {
        int chunk = h * 4 + c;
        cp16(dst + row * 128 + ((chunk ^ (row & 7)) << 4), tab + g + chunk * 16);
    }
}
__device__ __forceinline__ void gather2_cp(uint32_t dG, uint32_t dH,
    const char* __restrict__ tg, const char* __restrict__ th,
    const int* __restrict__ idxT, int k, int nbase, int N, int t)
{
    int row = t >> 1, h = t & 1;
    int n = nbase + row; if (n >= N) n = N - 1;
    size_t g = (size_t)idxT[(size_t)k * N + n] * 128;
#pragma unroll
    for (int c = 0; c < 4; ++c) {
        int chunk = h * 4 + c;
        int sw = row * 128 + ((chunk ^ (row & 7)) << 4);
        cp16(dG + sw, tg + g + chunk * 16);
        cp16(dH + sw, th + g + chunk * 16);
    }
}
__device__ __forceinline__ void stageW_cp(uint32_t dst,
    const __half* gh, const __half* gl, const __half* hh, const __half* hl, int t)
{
    cp16(dst + t * 16,          (const char*)gh + t * 16);
    cp16(dst + 4096 + t * 16,   (const char*)gh + 4096 + t * 16);
    cp16(dst + 8192 + t * 16,   (const char*)gl + t * 16);
    cp16(dst + 12288 + t * 16,  (const char*)gl + 4096 + t * 16);
    cp16(dst + 16384 + t * 16,  (const char*)hh + t * 16);
    cp16(dst + 20480 + t * 16,  (const char*)hh + 4096 + t * 16);
    cp16(dst + 24576 + t * 16,  (const char*)hl + t * 16);
    cp16(dst + 28672 + t * 16,  (const char*)hl + 4096 + t * 16);
}

// --------- MMA core (R12-identical): f16 A plane, B hi+lo ---------------
__device__ __forceinline__ void mma_core(float acc[2][8][4],
    uint32_t aT, uint32_t bHi, uint32_t bLo, int wl, int lr, int lc)
{
    const int arow = (wl * 32 + lr) * 128;
    const int axor = lr & 7;
#pragma unroll
    for (int ks = 0; ks < 4; ++ks) {
        uint32_t a[2][4];
        const int ac = ((ks * 2 + lc) ^ axor) << 4;
#pragma unroll
        for (int mt = 0; mt < 2; ++mt)
            ldsm4(a[mt], aT + arow + mt * 2048 + ac);
        const int brow = ks * 2048 + lr * 128;
#pragma unroll
        for (int np = 0; np < 4; ++np) {
            uint32_t bd = brow + (((2 * np + lc) ^ axor) << 4);
            uint32_t bh[4], bl[4];
            ldsm4t(bh, bHi + bd);
            ldsm4t(bl, bLo + bd);
#pragma unroll
            for (int mt = 0; mt < 2; ++mt) {
#pragma unroll
                for (int j = 0; j < 2; ++j) {
                    float* d = acc[mt][np * 2 + j];
                    mma_f16(d, a[mt], &bh[j * 2]);
                    mma_f16(d, a[mt], &bl[j * 2]);
                }
            }
        }
    }
}

__device__ __forceinline__ void acc_to_tile(char* sm, int base,
    float acc[2][8][4], int wl, int gID, int tig)
{
#pragma unroll
    for (int mt = 0; mt < 2; ++mt) {
        int r0 = wl * 32 + mt * 16 + gID;
        int r1 = r0 + 8;
#pragma unroll
        for (int nt = 0; nt < 8; ++nt) {
            uint32_t p0 = pack_h2(lrelu(acc[mt][nt][0]), lrelu(acc[mt][nt][1]));
            uint32_t p1 = pack_h2(lrelu(acc[mt][nt][2]), lrelu(acc[mt][nt][3]));
            *(uint32_t*)(sm + base + r0 * 128 + ((nt ^ (r0 & 7)) << 4) + tig * 4) = p0;
            *(uint32_t*)(sm + base + r1 * 128 + ((nt ^ (r1 & 7)) << 4) + tig * 4) = p1;
        }
    }
}

// ---------------------------------------------------------------------------
// kconvA: A double-buffered (prefetched gather), W single (sync-staged);
// shared gather; warps 0-3 g, 4-7 h. Outputs f16 tables. 3 blocks/SM.
// ---------------------------------------------------------------------------
__global__ __launch_bounds__(256, 3)
void kconvA_mma(const char* __restrict__ srcTab, const int* __restrict__ idxT,
                const __half* w1gh, const __half* w1gl,
                const __half* w1hh, const __half* w1hl,
                const __half* w2gh, const __half* w2gl,
                const __half* w2hh, const __half* w2hl,
                char* __restrict__ outgb, char* __restrict__ outhb, int N)
{
    extern __shared__ char sm[];
    const uint32_t sb = smem_u32(sm);
    const int t = threadIdx.x;
    const int lane = t & 31, w = t >> 5;
    const int b = w >> 2, wl = w & 3;
    const int lr = ((lane >> 3) & 1) * 8 + (lane & 7);
    const int lc = lane >> 4;
    const int gID = lane >> 2, tig = lane & 3;
    const int nbase = blockIdx.x * TM;

    float acc[2][8][4];
#pragma unroll
    for (int mt = 0; mt < 2; ++mt)
#pragma unroll
        for (int nt = 0; nt < 8; ++nt)
#pragma unroll
            for (int q = 0; q < 4; ++q) acc[mt][nt][q] = 0.f;

    // prologue: gather k=0 -> A0 (its own group)
    gather_cp(sb + A_A0, srcTab, idxT, 0, nbase, N, t);
    CP_COMMIT();

    for (int k = 0; k < KNB; ++k) {
        const uint32_t curA = (k & 1) ? A_A1 : A_A0;
        const uint32_t nxtA = (k & 1) ? A_A0 : A_A1;
        __syncthreads();   // mma(k-1) done: W and A[nxt] free
        stageW_cp(sb + A_W, w1gh + k * 4096, w1gl + k * 4096,
                  w1hh + k * 4096, w1hl + k * 4096, t);
        CP_COMMIT();       // [W(k)]
        if (k + 1 < KNB) {
            gather_cp(sb + nxtA, srcTab, idxT, k + 1, nbase, N, t);
            CP_COMMIT();   // [G(k+1)]
            CP_WAIT1();    // G(k), W(k) done; G(k+1) in flight
        } else {
            CP_WAIT0();
        }
        __syncthreads();
        mma_core(acc, sb + curA, sb + A_W + b * 16384,
                 sb + A_W + b * 16384 + 8192, wl, lr, lc);
    }

    // hidden = lrelu(conv1): g -> A0, h -> A1; W2 planes -> W
    __syncthreads();
    acc_to_tile(sm, b ? A_A1 : A_A0, acc, wl, gID, tig);
    stageW_cp(sb + A_W, w2gh, w2gl, w2hh, w2hl, t);
    CP_COMMIT();
    CP_WAIT0();
    __syncthreads();

#pragma unroll
    for (int mt = 0; mt < 2; ++mt)
#pragma unroll
        for (int nt = 0; nt < 8; ++nt)
#pragma unroll
            for (int q = 0; q < 4; ++q) acc[mt][nt][q] = 0.f;

    mma_core(acc, sb + (b ? A_A1 : A_A0), sb + A_W + b * 16384,
             sb + A_W + b * 16384 + 8192, wl, lr, lc);

    // store lrelu(hidden2) as f16 table
    char* outb = b ? outhb : outgb;
#pragma unroll
    for (int mt = 0; mt < 2; ++mt) {
        int n0 = nbase + wl * 32 + mt * 16 + gID;
        int n1 = n0 + 8;
#pragma unroll
        for (int nt = 0; nt < 8; ++nt) {
            int c = nt * 8 + tig * 2;
            if (n0 < N)
                *(uint32_t*)(outb + (size_t)n0 * 128 + c * 2) =
                    pack_h2(lrelu(acc[mt][nt][0]), lrelu(acc[mt][nt][1]));
            if (n1 < N)
                *(uint32_t*)(outb + (size_t)n1 * 128 + c * 2) =
                    pack_h2(lrelu(acc[mt][nt][2]), lrelu(acc[mt][nt][3]));
        }
    }
}

// ---------------------------------------------------------------------------
// kconvB: synchronous loop (R8 pattern), 64KB -> 3 blocks/SM; fused epilogue.
// ---------------------------------------------------------------------------
__global__ __launch_bounds__(256, 3)
void kconvB_mma(const char* __restrict__ tg, const char* __restrict__ th,
                const int* __restrict__ idxT,
                const __half* w3gh, const __half* w3gl,
                const __half* w3hh, const __half* w3hl,
                const float* __restrict__ xpart,
                float* __restrict__ outp, char* __restrict__ bfout, int N)
{
    extern __shared__ char sm[];
    const uint32_t sb = smem_u32(sm);
    const int t = threadIdx.x;
    const int lane = t & 31, w = t >> 5;
    const int b = w >> 2, wl = w & 3;
    const int lr = ((lane >> 3) & 1) * 8 + (lane & 7);
    const int lc = lane >> 4;
    const int gID = lane >> 2, tig = lane & 3;
    const int nbase = blockIdx.x * TM;

    float acc[2][8][4];
#pragma unroll
    for (int mt = 0; mt < 2; ++mt)
#pragma unroll
        for (int nt = 0; nt < 8; ++nt)
#pragma unroll
            for (int q = 0; q < 4; ++q) acc[mt][nt][q] = 0.f;

    const uint32_t aT = sb + (b ? B_AH : B_AG);

    for (int k = 0; k < KNB; ++k) {
        __syncthreads();
        gather2_cp(sb + B_AG, sb + B_AH, tg, th, idxT, k, nbase, N, t);
        stageW_cp(sb + B_W, w3gh + k * 4096, w3gl + k * 4096,
                  w3hh + k * 4096, w3hl + k * 4096, t);
        CP_COMMIT();
        CP_WAIT0();
        __syncthreads();
        mma_core(acc, aT, sb + B_W + b * 16384,
                 sb + B_W + b * 16384 + 8192, wl, lr, lc);
    }

    // epilogue: h warps publish H f32 (stride-68); g warps combine and store
    __syncthreads();
    float* hs = (float*)sm;
    if (b == 1) {
#pragma unroll
        for (int mt = 0; mt < 2; ++mt) {
            int r0 = wl * 32 + mt * 16 + gID;
            int r1 = r0 + 8;
#pragma unroll
            for (int nt = 0; nt < 8; ++nt) {
                int c = nt * 8 + tig * 2;
                *(float2*)(hs + r0 * 68 + c) = make_float2(acc[mt][nt][0], acc[mt][nt][1]);
                *(float2*)(hs + r1 * 68 + c) = make_float2(acc[mt][nt][2], acc[mt][nt][3]);
            }
        }
    }
    __syncthreads();
    if (b == 0) {
#pragma unroll
        for (int mt = 0; mt < 2; ++mt) {
#pragma unroll
            for (int half = 0; half < 2; ++half) {
                int r = wl * 32 + mt * 16 + half * 8 + gID;
                int n = nbase + r;
                if (n >= N) continue;
#pragma unroll
                for (int nt = 0; nt < 8; ++nt) {
                    int c = nt * 8 + tig * 2;
                    float g0 = acc[mt][nt][half * 2 + 0];
                    float g1 = acc[mt][nt][half * 2 + 1];
                    float2 hv = *(const float2*)(hs + r * 68 + c);
                    float2 xv = *(const float2*)(xpart + (size_t)n * 128 + c);
                    float2 y;
                    y.x = fmaf(xv.x, expf(tanhf(0.5f * g0)), hv.x);
                    y.y = fmaf(xv.y, expf(tanhf(0.5f * g1)), hv.y);
                    *(float2*)(outp + (size_t)n * 128 + c) = y;
                    if (bfout)
                        *(uint32_t*)(bfout + (size_t)n * 128 + c * 2) = pack_h2(y.x, y.y);
                }
            }
        }
    }
}

// ---------------------------------------------------------------------------
extern "C" void kernel_launch(void* const* d_in, const int* in_sizes, int n_in,
                              void* d_out, int out_size)
{
    const float* x     = (const float*)d_in[0];
    const int*   nbr   = (const int*)d_in[1];
    const float* g1_w1 = (const float*)d_in[2];
    const float* g1_w2 = (const float*)d_in[3];
    const float* g1_w3 = (const float*)d_in[4];
    const float* g2_w1 = (const float*)d_in[5];
    const float* g2_w2 = (const float*)d_in[6];
    const float* g2_w3 = (const float*)d_in[7];
    const float* h1_w1 = (const float*)d_in[8];
    const float* h1_w2 = (const float*)d_in[9];
    const float* h1_w3 = (const float*)d_in[10];
    const float* h2_w1 = (const float*)d_in[11];
    const float* h2_w2 = (const float*)d_in[12];
    const float* h2_w3 = (const float*)d_in[13];
    float* out = (float*)d_out;

    const int N = in_sizes[1] / KNB;
    const int blocks = (N + TM - 1) / TM;

    cudaFuncSetAttribute(kconvA_mma, cudaFuncAttributeMaxDynamicSharedMemorySize, SMEM_BYTES);
    cudaFuncSetAttribute(kconvB_mma, cudaFuncAttributeMaxDynamicSharedMemorySize, SMEM_BYTES);

    __half *wch, *wcl, *wdh, *wdl;
    cudaGetSymbolAddress((void**)&wch, g_wch);
    cudaGetSymbolAddress((void**)&wcl, g_wcl);
    cudaGetSymbolAddress((void**)&wdh, g_wdh);
    cudaGetSymbolAddress((void**)&wdl, g_wdl);
    int* idxT;   cudaGetSymbolAddress((void**)&idxT, g_idxT);
    char *x2b, *hgb, *hhb, *y1b;
    cudaGetSymbolAddress((void**)&x2b, g_x2b);
    cudaGetSymbolAddress((void**)&hgb, g_hgb);
    cudaGetSymbolAddress((void**)&hhb, g_hhb);
    cudaGetSymbolAddress((void**)&y1b, g_y1b);

    // conv tensor order: 0:g2w1 1:h2w1 2:g2w3 3:h2w3 4:g1w1 5:h1w1 6:g1w3 7:h1w3
    kprep_conv<<<(8 * 27 * 4096 + 255) / 256, 256>>>(
        g2_w1, h2_w1, g2_w3, h2_w3, g1_w1, h1_w1, g1_w3, h1_w3);
    // dense order: 0:g2w2 1:h2w2 2:g1w2 3:h1w2
    kprep_dense<<<(4 * 4096 + 255) / 256, 256>>>(g2_w2, h2_w2, g1_w2, h1_w2);
    kprep_idx<<<(N * KNB + 255) / 256, 256>>>(nbr, N);
    kprep_x2<<<(N * 32 + 255) / 256, 256>>>(x, N);

    const int CP = 27 * 4096;   // f16 elems per conv tensor

    // Stage 1: bottlenecks g2/h2 on x2 table (shared gather)
    kconvA_mma<<<blocks, 256, SMEM_BYTES>>>(
        x2b, idxT,
        wch + 0 * CP, wcl + 0 * CP, wch + 1 * CP, wcl + 1 * CP,
        wdh + 0 * 4096, wdl + 0 * 4096, wdh + 1 * 4096, wdl + 1 * 4096,
        hgb, hhb, N);
    // y1 = x1 * exp(tanh(G/2)) + H -> out[:, 0:64] (+ f16 table for stage 2)
    kconvB_mma<<<blocks, 256, SMEM_BYTES>>>(
        hgb, hhb, idxT,
        wch + 2 * CP, wcl + 2 * CP, wch + 3 * CP, wcl + 3 * CP,
        x /*x1*/, out /*y1*/, y1b, N);
    // Stage 2: bottlenecks g1/h1 on y1 table
    kconvA_mma<<<blocks, 256, SMEM_BYTES>>>(
        y1b, idxT,
        wch + 4 * CP, wcl + 4 * CP, wch + 5 * CP, wcl + 5 * CP,
        wdh + 2 * 4096, wdl + 2 * 4096, wdh + 3 * 4096, wdl + 3 * 4096,
        hgb, hhb, N);
    // y2 = x2 * exp(tanh(G2/2)) + H2 -> out[:, 64:128]
    kconvB_mma<<<blocks, 256, SMEM_BYTES>>>(
        hgb, hhb, idxT,
        wch + 6 * CP, wcl + 6 * CP, wch + 7 * CP, wcl + 7 * CP,
        x + 64 /*x2*/, out + 64 /*y2*/, nullptr, N);
}

// round 14
// speedup vs baseline: 1.9828x; 1.9828x over previous
#include <cuda_runtime.h>
#include <cuda_fp16.h>
#include <math.h>
#include <stdint.h>

#define TM      128
#define KNB     27
#define MAXN    150000

// kconvA: A0 16K | A1 16K | W0 16K | W1 16K = 64KB (all double-buffered)
#define A_A0   0
#define A_A1   16384
#define A_W0   32768
#define A_W1   49152
#define SMEM_A 65536
// kconvB: (Ag|Ah)0 32K | (Ag|Ah)1 32K | W0 16K | W1 16K = 96KB
#define B_ASTG 32768
#define B_W0   65536
#define B_W1   81920
#define SMEM_B 98304

// ------------------------- device scratch -------------------------
// f16 gather tables: row n = 128B (64 f16)
__device__ __align__(16) char g_x2b[(size_t)MAXN * 128];
__device__ __align__(16) char g_hgb[(size_t)MAXN * 128];
__device__ __align__(16) char g_hhb[(size_t)MAXN * 128];
__device__ __align__(16) char g_y1b[(size_t)MAXN * 128];
__device__ int g_idxT[KNB * MAXN];
// single-plane f16 W, swizzled [kk][n] (8 conv tensors x 27 planes; 4 dense)
__device__ __align__(16) __half g_wch[8 * 27 * 4096];
__device__ __align__(16) __half g_wdh[4 * 4096];

// ------------------------- helpers -------------------------
__device__ __forceinline__ uint32_t smem_u32(const void* p) {
    uint32_t a;
    asm("{ .reg .u64 t; cvta.to.shared.u64 t, %1; cvt.u32.u64 %0, t; }" : "=r"(a) : "l"(p));
    return a;
}
__device__ __forceinline__ float lrelu(float v) { return v >= 0.f ? v : 0.2f * v; }
__device__ __forceinline__ uint32_t pack_h2(float lo_elem, float hi_elem) {
    uint32_t r;
    asm("cvt.rn.f16x2.f32 %0, %1, %2;" : "=r"(r) : "f"(hi_elem), "f"(lo_elem));
    return r;
}
__device__ __forceinline__ void cp16(uint32_t dst, const char* src) {
    asm volatile("cp.async.cg.shared.global [%0], [%1], 16;" :: "r"(dst), "l"(src));
}
#define CP_COMMIT() asm volatile("cp.async.commit_group;" ::: "memory")
#define CP_WAIT0()  asm volatile("cp.async.wait_group 0;" ::: "memory")
#define CP_WAIT1()  asm volatile("cp.async.wait_group 1;" ::: "memory")

__device__ __forceinline__ void ldsm4(uint32_t* r, uint32_t a) {
    asm volatile("ldmatrix.sync.aligned.m8n8.x4.shared.b16 {%0,%1,%2,%3}, [%4];"
                 : "=r"(r[0]), "=r"(r[1]), "=r"(r[2]), "=r"(r[3]) : "r"(a));
}
__device__ __forceinline__ void ldsm4t(uint32_t* r, uint32_t a) {
    asm volatile("ldmatrix.sync.aligned.m8n8.x4.trans.shared.b16 {%0,%1,%2,%3}, [%4];"
                 : "=r"(r[0]), "=r"(r[1]), "=r"(r[2]), "=r"(r[3]) : "r"(a));
}
__device__ __forceinline__ void mma_f16(float* d, const uint32_t* a, const uint32_t* b) {
    asm volatile(
        "mma.sync.aligned.m16n8k16.row.col.f32.f16.f16.f32 "
        "{%0,%1,%2,%3}, {%4,%5,%6,%7}, {%8,%9}, {%0,%1,%2,%3};"
        : "+f"(d[0]), "+f"(d[1]), "+f"(d[2]), "+f"(d[3])
        : "r"(a[0]), "r"(a[1]), "r"(a[2]), "r"(a[3]), "r"(b[0]), "r"(b[1]));
}

// ------------------------- prep kernels -------------------------
// W planes: [kk][n], 128B rows, 16B chunk XOR (kk & 7); single f16 plane
__global__ void kprep_conv(const float* w0, const float* w1, const float* w2,
                           const float* w3, const float* w4, const float* w5,
                           const float* w6, const float* w7) {
    int e = blockIdx.x * 256 + threadIdx.x;
    const int per = 27 * 4096;
    if (e >= 8 * per) return;
    int ti = e / per, r = e % per;
    int k = r >> 12, p = r & 4095;
    int kk = p >> 6, n = p & 63;
    const float* ws[8] = {w0, w1, w2, w3, w4, w5, w6, w7};
    float v = ws[ti][(size_t)k * 4096 + kk * 64 + n];
    int off = kk * 128 + (((n >> 3) ^ (kk & 7)) << 4) + (n & 7) * 2;
    *(__half*)((char*)g_wch + ((size_t)ti * 27 + k) * 8192 + off) = __float2half_rn(v);
}
__global__ void kprep_dense(const float* w0, const float* w1,
                            const float* w2, const float* w3) {
    int e = blockIdx.x * 256 + threadIdx.x;
    if (e >= 4 * 4096) return;
    int ti = e >> 12, p = e & 4095;
    int kk = p >> 6, n = p & 63;
    const float* ws[4] = {w0, w1, w2, w3};
    float v = ws[ti][kk * 64 + n];
    int off = kk * 128 + (((n >> 3) ^ (kk & 7)) << 4) + (n & 7) * 2;
    *(__half*)((char*)g_wdh + (size_t)ti * 8192 + off) = __float2half_rn(v);
}
__global__ void kprep_idx(const int* __restrict__ idx, int N) {
    int e = blockIdx.x * 256 + threadIdx.x;
    if (e >= N * KNB) return;
    g_idxT[(size_t)(e % KNB) * N + (e / KNB)] = idx[e];
}
__global__ void kprep_x2(const float* __restrict__ x, int N) {
    int e = blockIdx.x * 256 + threadIdx.x;
    if (e >= N * 32) return;
    int n = e >> 5, c = (e & 31) * 2;
    float v0 = x[(size_t)n * 128 + 64 + c];
    float v1 = x[(size_t)n * 128 + 64 + c + 1];
    *(uint32_t*)(g_x2b + (size_t)n * 128 + c * 2) = pack_h2(v0, v1);
}

// ------------------------- staging (256 threads) -------------------------
__device__ __forceinline__ void gather_cp(uint32_t dst,
    const char* __restrict__ tab, const int* __restrict__ idxT,
    int k, int nbase, int N, int t)
{
    int row = t >> 1, h = t & 1;
    int n = nbase + row; if (n >= N) n = N - 1;
    size_t g = (size_t)idxT[(size_t)k * N + n] * 128;
#pragma unroll
    for (int c = 0; c < 4; ++c) {
        int chunk = h * 4 + c;
        cp16(dst + row * 128 + ((chunk ^ (row & 7)) << 4), tab + g + chunk * 16);
    }
}
__device__ __forceinline__ void gather2_cp(uint32_t dG, uint32_t dH,
    const char* __restrict__ tg, const char* __restrict__ th,
    const int* __restrict__ idxT, int k, int nbase, int N, int t)
{
    int row = t >> 1, h = t & 1;
    int n = nbase + row; if (n >= N) n = N - 1;
    size_t g = (size_t)idxT[(size_t)k * N + n] * 128;
#pragma unroll
    for (int c = 0; c < 4; ++c) {
        int chunk = h * 4 + c;
        int sw = row * 128 + ((chunk ^ (row & 7)) << 4);
        cp16(dG + sw, tg + g + chunk * 16);
        cp16(dH + sw, th + g + chunk * 16);
    }
}
// stage 16KB W (g plane 8K | h plane 8K)
__device__ __forceinline__ void stageW_cp(uint32_t dst,
    const __half* gw, const __half* hw, int t)
{
    cp16(dst + t * 16,          (const char*)gw + t * 16);
    cp16(dst + 4096 + t * 16,   (const char*)gw + 4096 + t * 16);
    cp16(dst + 8192 + t * 16,   (const char*)hw + t * 16);
    cp16(dst + 12288 + t * 16,  (const char*)hw + 4096 + t * 16);
}

// --------- MMA core: single f16 A plane x single f16 B plane -------------
__device__ __forceinline__ void mma_core(float acc[2][8][4],
    uint32_t aT, uint32_t bT, int wl, int lr, int lc)
{
    const int arow = (wl * 32 + lr) * 128;
    const int axor = lr & 7;
#pragma unroll
    for (int ks = 0; ks < 4; ++ks) {
        uint32_t a[2][4];
        const int ac = ((ks * 2 + lc) ^ axor) << 4;
#pragma unroll
        for (int mt = 0; mt < 2; ++mt)
            ldsm4(a[mt], aT + arow + mt * 2048 + ac);
        const int brow = ks * 2048 + lr * 128;
#pragma unroll
        for (int np = 0; np < 4; ++np) {
            uint32_t bd = brow + (((2 * np + lc) ^ axor) << 4);
            uint32_t bf[4];
            ldsm4t(bf, bT + bd);
#pragma unroll
            for (int mt = 0; mt < 2; ++mt) {
#pragma unroll
                for (int j = 0; j < 2; ++j)
                    mma_f16(acc[mt][np * 2 + j], a[mt], &bf[j * 2]);
            }
        }
    }
}

__device__ __forceinline__ void acc_to_tile(char* sm, int base,
    float acc[2][8][4], int wl, int gID, int tig)
{
#pragma unroll
    for (int mt = 0; mt < 2; ++mt) {
        int r0 = wl * 32 + mt * 16 + gID;
        int r1 = r0 + 8;
#pragma unroll
        for (int nt = 0; nt < 8; ++nt) {
            uint32_t p0 = pack_h2(lrelu(acc[mt][nt][0]), lrelu(acc[mt][nt][1]));
            uint32_t p1 = pack_h2(lrelu(acc[mt][nt][2]), lrelu(acc[mt][nt][3]));
            *(uint32_t*)(sm + base + r0 * 128 + ((nt ^ (r0 & 7)) << 4) + tig * 4) = p0;
            *(uint32_t*)(sm + base + r1 * 128 + ((nt ^ (r1 & 7)) << 4) + tig * 4) = p1;
        }
    }
}

// ---------------------------------------------------------------------------
// kconvA: A + W double-buffered; shared gather; warps 0-3 g, 4-7 h.
// ---------------------------------------------------------------------------
__global__ __launch_bounds__(256, 2)
void kconvA_mma(const char* __restrict__ srcTab, const int* __restrict__ idxT,
                const __half* w1g, const __half* w1h,
                const __half* w2g, const __half* w2h,
                char* __restrict__ outgb, char* __restrict__ outhb, int N)
{
    extern __shared__ char sm[];
    const uint32_t sb = smem_u32(sm);
    const int t = threadIdx.x;
    const int lane = t & 31, w = t >> 5;
    const int b = w >> 2, wl = w & 3;
    const int lr = ((lane >> 3) & 1) * 8 + (lane & 7);
    const int lc = lane >> 4;
    const int gID = lane >> 2, tig = lane & 3;
    const int nbase = blockIdx.x * TM;

    float acc[2][8][4];
#pragma unroll
    for (int mt = 0; mt < 2; ++mt)
#pragma unroll
        for (int nt = 0; nt < 8; ++nt)
#pragma unroll
            for (int q = 0; q < 4; ++q) acc[mt][nt][q] = 0.f;

    // prologue: stage k=0 into buffer 0
    gather_cp(sb + A_A0, srcTab, idxT, 0, nbase, N, t);
    stageW_cp(sb + A_W0, w1g, w1h, t);
    CP_COMMIT();

    for (int k = 0; k < KNB; ++k) {
        const uint32_t curA = (k & 1) ? A_A1 : A_A0;
        const uint32_t nxtA = (k & 1) ? A_A0 : A_A1;
        const uint32_t curW = (k & 1) ? A_W1 : A_W0;
        const uint32_t nxtW = (k & 1) ? A_W0 : A_W1;
        __syncthreads();            // mma(k-1) done: nxt buffers free
        if (k + 1 < KNB) {
            gather_cp(sb + nxtA, srcTab, idxT, k + 1, nbase, N, t);
            stageW_cp(sb + nxtW, w1g + (k + 1) * 4096, w1h + (k + 1) * 4096, t);
            CP_COMMIT();
            CP_WAIT1();             // stage(k) done; stage(k+1) in flight
        } else {
            CP_WAIT0();
        }
        __syncthreads();
        mma_core(acc, sb + curA, sb + curW + b * 8192, wl, lr, lc);
    }

    // hidden = lrelu(conv1): g -> A0, h -> A1; W2 plane -> W0
    __syncthreads();
    acc_to_tile(sm, b ? A_A1 : A_A0, acc, wl, gID, tig);
    stageW_cp(sb + A_W0, w2g, w2h, t);
    CP_COMMIT();
    CP_WAIT0();
    __syncthreads();

#pragma unroll
    for (int mt = 0; mt < 2; ++mt)
#pragma unroll
        for (int nt = 0; nt < 8; ++nt)
#pragma unroll
            for (int q = 0; q < 4; ++q) acc[mt][nt][q] = 0.f;

    mma_core(acc, sb + (b ? A_A1 : A_A0), sb + A_W0 + b * 8192, wl, lr, lc);

    // store lrelu(hidden2) as f16 table
    char* outb = b ? outhb : outgb;
#pragma unroll
    for (int mt = 0; mt < 2; ++mt) {
        int n0 = nbase + wl * 32 + mt * 16 + gID;
        int n1 = n0 + 8;
#pragma unroll
        for (int nt = 0; nt < 8; ++nt) {
            int c = nt * 8 + tig * 2;
            if (n0 < N)
                *(uint32_t*)(outb + (size_t)n0 * 128 + c * 2) =
                    pack_h2(lrelu(acc[mt][nt][0]), lrelu(acc[mt][nt][1]));
            if (n1 < N)
                *(uint32_t*)(outb + (size_t)n1 * 128 + c * 2) =
                    pack_h2(lrelu(acc[mt][nt][2]), lrelu(acc[mt][nt][3]));
        }
    }
}

// ---------------------------------------------------------------------------
// kconvB: A-pair + W double-buffered; fused coupling epilogue.
// ---------------------------------------------------------------------------
__global__ __launch_bounds__(256, 2)
void kconvB_mma(const char* __restrict__ tg, const char* __restrict__ th,
                const int* __restrict__ idxT,
                const __half* w3g, const __half* w3h,
                const float* __restrict__ xpart,
                float* __restrict__ outp, char* __restrict__ bfout, int N)
{
    extern __shared__ char sm[];
    const uint32_t sb = smem_u32(sm);
    const int t = threadIdx.x;
    const int lane = t & 31, w = t >> 5;
    const int b = w >> 2, wl = w & 3;
    const int lr = ((lane >> 3) & 1) * 8 + (lane & 7);
    const int lc = lane >> 4;
    const int gID = lane >> 2, tig = lane & 3;
    const int nbase = blockIdx.x * TM;

    float acc[2][8][4];
#pragma unroll
    for (int mt = 0; mt < 2; ++mt)
#pragma unroll
        for (int nt = 0; nt < 8; ++nt)
#pragma unroll
            for (int q = 0; q < 4; ++q) acc[mt][nt][q] = 0.f;

    // prologue: stage k=0 into buffer 0 (A pair + W)
    gather2_cp(sb + 0, sb + 16384, tg, th, idxT, 0, nbase, N, t);
    stageW_cp(sb + B_W0, w3g, w3h, t);
    CP_COMMIT();

    for (int k = 0; k < KNB; ++k) {
        const uint32_t curA = (uint32_t)(k & 1) * B_ASTG;
        const uint32_t nxtA = (uint32_t)((k + 1) & 1) * B_ASTG;
        const uint32_t curW = (k & 1) ? B_W1 : B_W0;
        const uint32_t nxtW = (k & 1) ? B_W0 : B_W1;
        __syncthreads();
        if (k + 1 < KNB) {
            gather2_cp(sb + nxtA, sb + nxtA + 16384, tg, th, idxT, k + 1, nbase, N, t);
            stageW_cp(sb + nxtW, w3g + (k + 1) * 4096, w3h + (k + 1) * 4096, t);
            CP_COMMIT();
            CP_WAIT1();
        } else {
            CP_WAIT0();
        }
        __syncthreads();
        mma_core(acc, sb + curA + (b ? 16384u : 0u), sb + curW + b * 8192, wl, lr, lc);
    }

    // epilogue: h warps publish H f32 (stride-68); g warps combine and store
    __syncthreads();
    float* hs = (float*)sm;
    if (b == 1) {
#pragma unroll
        for (int mt = 0; mt < 2; ++mt) {
            int r0 = wl * 32 + mt * 16 + gID;
            int r1 = r0 + 8;
#pragma unroll
            for (int nt = 0; nt < 8; ++nt) {
                int c = nt * 8 + tig * 2;
                *(float2*)(hs + r0 * 68 + c) = make_float2(acc[mt][nt][0], acc[mt][nt][1]);
                *(float2*)(hs + r1 * 68 + c) = make_float2(acc[mt][nt][2], acc[mt][nt][3]);
            }
        }
    }
    __syncthreads();
    if (b == 0) {
#pragma unroll
        for (int mt = 0; mt < 2; ++mt) {
#pragma unroll
            for (int half = 0; half < 2; ++half) {
                int r = wl * 32 + mt * 16 + half * 8 + gID;
                int n = nbase + r;
                if (n >= N) continue;
#pragma unroll
                for (int nt = 0; nt < 8; ++nt) {
                    int c = nt * 8 + tig * 2;
                    float g0 = acc[mt][nt][half * 2 + 0];
                    float g1 = acc[mt][nt][half * 2 + 1];
                    float2 hv = *(const float2*)(hs + r * 68 + c);
                    float2 xv = *(const float2*)(xpart + (size_t)n * 128 + c);
                    float2 y;
                    y.x = fmaf(xv.x, expf(tanhf(0.5f * g0)), hv.x);
                    y.y = fmaf(xv.y, expf(tanhf(0.5f * g1)), hv.y);
                    *(float2*)(outp + (size_t)n * 128 + c) = y;
                    if (bfout)
                        *(uint32_t*)(bfout + (size_t)n * 128 + c * 2) = pack_h2(y.x, y.y);
                }
            }
        }
    }
}

// ---------------------------------------------------------------------------
extern "C" void kernel_launch(void* const* d_in, const int* in_sizes, int n_in,
                              void* d_out, int out_size)
{
    const float* x     = (const float*)d_in[0];
    const int*   nbr   = (const int*)d_in[1];
    const float* g1_w1 = (const float*)d_in[2];
    const float* g1_w2 = (const float*)d_in[3];
    const float* g1_w3 = (const float*)d_in[4];
    const float* g2_w1 = (const float*)d_in[5];
    const float* g2_w2 = (const float*)d_in[6];
    const float* g2_w3 = (const float*)d_in[7];
    const float* h1_w1 = (const float*)d_in[8];
    const float* h1_w2 = (const float*)d_in[9];
    const float* h1_w3 = (const float*)d_in[10];
    const float* h2_w1 = (const float*)d_in[11];
    const float* h2_w2 = (const float*)d_in[12];
    const float* h2_w3 = (const float*)d_in[13];
    float* out = (float*)d_out;

    const int N = in_sizes[1] / KNB;
    const int blocks = (N + TM - 1) / TM;

    cudaFuncSetAttribute(kconvA_mma, cudaFuncAttributeMaxDynamicSharedMemorySize, SMEM_A);
    cudaFuncSetAttribute(kconvB_mma, cudaFuncAttributeMaxDynamicSharedMemorySize, SMEM_B);

    __half *wch, *wdh;
    cudaGetSymbolAddress((void**)&wch, g_wch);
    cudaGetSymbolAddress((void**)&wdh, g_wdh);
    int* idxT;   cudaGetSymbolAddress((void**)&idxT, g_idxT);
    char *x2b, *hgb, *hhb, *y1b;
    cudaGetSymbolAddress((void**)&x2b, g_x2b);
    cudaGetSymbolAddress((void**)&hgb, g_hgb);
    cudaGetSymbolAddress((void**)&hhb, g_hhb);
    cudaGetSymbolAddress((void**)&y1b, g_y1b);

    // conv tensor order: 0:g2w1 1:h2w1 2:g2w3 3:h2w3 4:g1w1 5:h1w1 6:g1w3 7:h1w3
    kprep_conv<<<(8 * 27 * 4096 + 255) / 256, 256>>>(
        g2_w1, h2_w1, g2_w3, h2_w3, g1_w1, h1_w1, g1_w3, h1_w3);
    // dense order: 0:g2w2 1:h2w2 2:g1w2 3:h1w2
    kprep_dense<<<(4 * 4096 + 255) / 256, 256>>>(g2_w2, h2_w2, g1_w2, h1_w2);
    kprep_idx<<<(N * KNB + 255) / 256, 256>>>(nbr, N);
    kprep_x2<<<(N * 32 + 255) / 256, 256>>>(x, N);

    const int CP = 27 * 4096;   // f16 elems per conv tensor

    // Stage 1: bottlenecks g2/h2 on x2 table (shared gather)
    kconvA_mma<<<blocks, 256, SMEM_A>>>(
        x2b, idxT,
        wch + 0 * CP, wch + 1 * CP, wdh + 0 * 4096, wdh + 1 * 4096,
        hgb, hhb, N);
    // y1 = x1 * exp(tanh(G/2)) + H -> out[:, 0:64] (+ f16 table for stage 2)
    kconvB_mma<<<blocks, 256, SMEM_B>>>(
        hgb, hhb, idxT, wch + 2 * CP, wch + 3 * CP,
        x /*x1*/, out /*y1*/, y1b, N);
    // Stage 2: bottlenecks g1/h1 on y1 table
    kconvA_mma<<<blocks, 256, SMEM_A>>>(
        y1b, idxT,
        wch + 4 * CP, wch + 5 * CP, wdh + 2 * 4096, wdh + 3 * 4096,
        hgb, hhb, N);
    // y2 = x2 * exp(tanh(G2/2)) + H2 -> out[:, 64:128]
    kconvB_mma<<<blocks, 256, SMEM_B>>>(
        hgb, hhb, idxT, wch + 6 * CP, wch + 7 * CP,
        x + 64 /*x2*/, out + 64 /*y2*/, nullptr, N);
}